// round 13
// baseline (speedup 1.0000x reference)
#include <cuda_runtime.h>
#include <cuda_bf16.h>
#include <cstdint>

#define BB 4
#define TT 2048
#define DD 1024
#define HH 16
#define HD 64
#define NR (BB*TT)   // 8192

// ---------------- device scratch (allocation-free rule) ----------------
__device__ __nv_bfloat16 g_qb[NR*DD];        // [B,H,T,HD] bf16 (q pre-scaled by 0.125*log2e)
__device__ __nv_bfloat16 g_kb[NR*DD];
__device__ __nv_bfloat16 g_vb[NR*DD];
__device__ __nv_bfloat16 g_xnh[NR*DD];       // layernormed x, bf16
__device__ __nv_bfloat16 g_aoh[NR*DD];       // attention out bf16 [B*T, D]
__device__ __nv_bfloat16 g_wh[4u*DD*DD];     // Wq,Wk,Wv,Wo bf16

__device__ __forceinline__ uint32_t smem_u32(const void* p) {
    uint32_t a;
    asm("{ .reg .u64 t; cvta.to.shared.u64 t, %1; cvt.u32.u64 %0, t; }" : "=r"(a) : "l"(p));
    return a;
}
__device__ __forceinline__ uint32_t packbf(float a, float b) {
    __nv_bfloat162 t = __floats2bfloat162_rn(a, b);
    return *(uint32_t*)&t;
}

// mma / ldmatrix / cp.async helpers
__device__ __forceinline__ void mma16816(float (&c)[4], const uint32_t (&a)[4],
                                         uint32_t b0, uint32_t b1) {
    asm volatile(
        "mma.sync.aligned.m16n8k16.row.col.f32.bf16.bf16.f32 "
        "{%0,%1,%2,%3},{%4,%5,%6,%7},{%8,%9},{%0,%1,%2,%3};"
        : "+f"(c[0]), "+f"(c[1]), "+f"(c[2]), "+f"(c[3])
        : "r"(a[0]), "r"(a[1]), "r"(a[2]), "r"(a[3]), "r"(b0), "r"(b1));
}
__device__ __forceinline__ void ldm_x4(uint32_t (&r)[4], uint32_t addr) {
    asm volatile("ldmatrix.sync.aligned.m8n8.x4.shared.b16 {%0,%1,%2,%3}, [%4];"
                 : "=r"(r[0]), "=r"(r[1]), "=r"(r[2]), "=r"(r[3]) : "r"(addr));
}
__device__ __forceinline__ void ldm_x4_t(uint32_t (&r)[4], uint32_t addr) {
    asm volatile("ldmatrix.sync.aligned.m8n8.x4.trans.shared.b16 {%0,%1,%2,%3}, [%4];"
                 : "=r"(r[0]), "=r"(r[1]), "=r"(r[2]), "=r"(r[3]) : "r"(addr));
}
__device__ __forceinline__ void cp16(uint32_t s, const void* g) {
    asm volatile("cp.async.cg.shared.global [%0], [%1], 16;" :: "r"(s), "l"(g));
}
__device__ __forceinline__ void cp_commit() { asm volatile("cp.async.commit_group;"); }
__device__ __forceinline__ void cp_wait2()  { asm volatile("cp.async.wait_group 2;"); }
__device__ __forceinline__ void cp_wait1()  { asm volatile("cp.async.wait_group 1;"); }
__device__ __forceinline__ void cp_wait0()  { asm volatile("cp.async.wait_group 0;"); }

// ---------------------------------------------------------------------------
// Weight convert: fp32 -> bf16 for Wq,Wk,Wv,Wo
// ---------------------------------------------------------------------------
__global__ void wconv_kernel(const float* __restrict__ Wq, const float* __restrict__ Wk,
                             const float* __restrict__ Wv, const float* __restrict__ Wo) {
    int m = blockIdx.y;
    const float* W = (m == 0) ? Wq : (m == 1) ? Wk : (m == 2) ? Wv : Wo;
    size_t base = (size_t)m * DD * DD;
    int idx = blockIdx.x * 256 + threadIdx.x;
    float4 v = ((const float4*)W)[idx];
    __nv_bfloat162* dh = (__nv_bfloat162*)(g_wh + base + (size_t)idx * 4);
    dh[0] = __floats2bfloat162_rn(v.x, v.y);
    dh[1] = __floats2bfloat162_rn(v.z, v.w);
}

// ---------------------------------------------------------------------------
// LayerNorm -> bf16
// ---------------------------------------------------------------------------
__global__ void ln_kernel(const float* __restrict__ x,
                          const float* __restrict__ gamma,
                          const float* __restrict__ beta) {
    int row = blockIdx.x;
    int t = threadIdx.x;
    const float4* xr = (const float4*)(x + (size_t)row * DD);
    float4 v = xr[t];
    float s  = v.x + v.y + v.z + v.w;
    float sq = v.x*v.x + v.y*v.y + v.z*v.z + v.w*v.w;

    __shared__ float red0[8], red1[8];
    #pragma unroll
    for (int o = 16; o > 0; o >>= 1) {
        s  += __shfl_xor_sync(0xffffffffu, s,  o);
        sq += __shfl_xor_sync(0xffffffffu, sq, o);
    }
    int w = t >> 5, l = t & 31;
    if (l == 0) { red0[w] = s; red1[w] = sq; }
    __syncthreads();
    __shared__ float smu, srs;
    if (t < 32) {
        float a  = (t < 8) ? red0[t] : 0.f;
        float b2 = (t < 8) ? red1[t] : 0.f;
        #pragma unroll
        for (int o = 4; o > 0; o >>= 1) {
            a  += __shfl_xor_sync(0xffffffffu, a,  o);
            b2 += __shfl_xor_sync(0xffffffffu, b2, o);
        }
        if (t == 0) {
            float mu = a * (1.0f / DD);
            float var = b2 * (1.0f / DD) - mu * mu;
            smu = mu; srs = rsqrtf(var + 1e-5f);
        }
    }
    __syncthreads();
    float mu = smu, rs = srs;
    float4 gv = ((const float4*)gamma)[t];
    float4 bv = ((const float4*)beta)[t];
    float o0 = (v.x - mu) * rs * gv.x + bv.x;
    float o1 = (v.y - mu) * rs * gv.y + bv.y;
    float o2 = (v.z - mu) * rs * gv.z + bv.z;
    float o3 = (v.w - mu) * rs * gv.w + bv.w;
    size_t off = (size_t)row * DD + t * 4;
    ((__nv_bfloat162*)(g_xnh + off))[0] = __floats2bfloat162_rn(o0, o1);
    ((__nv_bfloat162*)(g_xnh + off))[1] = __floats2bfloat162_rn(o2, o3);
}

// ---------------------------------------------------------------------------
// Tensor-core GEMM core. 128x128 tile, k-chunk 32, 8 warps 4(m)x2(n).
// 4-stage cp.async pipeline (prefetch depth 3), ONE __syncthreads per chunk.
// acc = Ah @ Bh^T (1 mma). Stage: Ah, Bh (20480 B), row pitch 80 B.
// ---------------------------------------------------------------------------
#define SPITCH 40            // elements per row (80 bytes)
#define GMATB  10240
#define GSTAGEB (2 * GMATB)          // 20480
#define GEMM_DSMEM (4 * GSTAGEB)     // 81920
#define NKC (DD / 32)                // 32

__device__ __forceinline__ void gemm_issue(
    const __nv_bfloat16* Ahg, const __nv_bfloat16* Bhg,
    uint32_t base, int kc, int tid)
{
    #pragma unroll
    for (int u = 0; u < 2; u++) {
        int idx = tid * 2 + u;                 // 0..511
        int row = idx >> 2;
        int sg  = idx & 3;                     // 16B segment
        uint32_t so = (uint32_t)(row * 80 + sg * 16);
        size_t ge = (size_t)row * DD + kc * 32 + sg * 8;
        cp16(base + so,         Ahg + ge);
        cp16(base + GMATB + so, Bhg + ge);
    }
    cp_commit();
}

__device__ __forceinline__ void gemm_core(
    const __nv_bfloat16* __restrict__ Ahg, const __nv_bfloat16* __restrict__ Bhg,
    char* dsm, float (&acc)[2][8][4], int tid)
{
    int lane = tid & 31;
    int w = tid >> 5;
    int wm = w & 3;
    int wn = w >> 2;

    uint32_t sb0 = smem_u32(dsm);
    int a_row = (lane & 15), a_cg = (lane >> 4) * 8;
    int quad = lane >> 3;
    int b_row = (lane & 7) + ((quad & 2) ? 8 : 0);
    int b_col = (quad & 1) ? 8 : 0;

    gemm_issue(Ahg, Bhg, sb0,               0, tid);
    gemm_issue(Ahg, Bhg, sb0 + GSTAGEB,     1, tid);
    gemm_issue(Ahg, Bhg, sb0 + 2 * GSTAGEB, 2, tid);

    for (int kc = 0; kc < NKC; kc++) {
        if (kc < NKC - 2)       cp_wait2();
        else if (kc == NKC - 2) cp_wait1();
        else                    cp_wait0();
        __syncthreads();
        if (kc + 3 < NKC)
            gemm_issue(Ahg, Bhg, sb0 + ((kc + 3) & 3) * GSTAGEB, kc + 3, tid);

        uint32_t Ah_u = sb0 + (kc & 3) * GSTAGEB;
        uint32_t Bh_u = Ah_u + GMATB;

        #pragma unroll
        for (int ks = 0; ks < 2; ks++) {
            uint32_t ah[2][4];
            #pragma unroll
            for (int mt = 0; mt < 2; mt++) {
                uint32_t off = (uint32_t)((wm * 32 + mt * 16 + a_row) * SPITCH + ks * 16 + a_cg) * 2;
                ldm_x4(ah[mt], Ah_u + off);
            }
            #pragma unroll
            for (int nt2 = 0; nt2 < 4; nt2++) {
                uint32_t boff = (uint32_t)((wn * 64 + nt2 * 16 + b_row) * SPITCH + ks * 16 + b_col) * 2;
                uint32_t bh[4];
                ldm_x4(bh, Bh_u + boff);
                int n0t = nt2 * 2, n1t = nt2 * 2 + 1;
                mma16816(acc[0][n0t], ah[0], bh[0], bh[1]);
                mma16816(acc[1][n0t], ah[1], bh[0], bh[1]);
                mma16816(acc[0][n1t], ah[0], bh[2], bh[3]);
                mma16816(acc[1][n1t], ah[1], bh[2], bh[3]);
            }
        }
    }
    __syncthreads();
}

// ---------------------------------------------------------------------------
// QKV projection -> bf16 [B,H,T,HD]; q pre-scaled by 0.125*log2e
// ---------------------------------------------------------------------------
__global__ void __launch_bounds__(256, 2) qkv_mma_kernel(
    const float* __restrict__ bq, const float* __restrict__ bk, const float* __restrict__ bv)
{
    extern __shared__ char dsm[];
    int tid = threadIdx.x;
    int z = blockIdx.z;
    int m0 = blockIdx.y * 128;
    int n0 = blockIdx.x * 128;

    const float* bias; __nv_bfloat16* dst; float sc;
    if (z == 0)      { bias = bq; dst = g_qb; sc = 0.125f * 1.44269504089f; }
    else if (z == 1) { bias = bk; dst = g_kb; sc = 1.0f; }
    else             { bias = bv; dst = g_vb; sc = 1.0f; }

    float acc[2][8][4] = {};
    gemm_core(g_xnh + (size_t)m0 * DD,
              g_wh + (size_t)z * DD * DD + (size_t)n0 * DD,
              dsm, acc, tid);

    int lane = tid & 31;
    int w = tid >> 5, wm = w & 3, wn = w >> 2;
    #pragma unroll
    for (int mt = 0; mt < 2; mt++) {
        #pragma unroll
        for (int nt = 0; nt < 8; nt++) {
            int r = m0 + wm * 32 + mt * 16 + (lane >> 2);
            int c = n0 + wn * 64 + nt * 8 + (lane & 3) * 2;
            float b0 = bias[c], b1 = bias[c + 1];
            #pragma unroll
            for (int rr = 0; rr < 2; rr++) {
                int row = r + rr * 8;
                int b = row >> 11, t = row & (TT - 1);
                int h = c >> 6, hd = c & 63;
                __nv_bfloat16* p = dst + (((size_t)(b * HH + h)) * TT + t) * HD + hd;
                float vx = (acc[mt][nt][rr * 2 + 0] + b0) * sc;
                float vy = (acc[mt][nt][rr * 2 + 1] + b1) * sc;
                *(__nv_bfloat162*)p = __floats2bfloat162_rn(vx, vy);
            }
        }
    }
}

// ---------------------------------------------------------------------------
// Output projection: out = x + ao @ Wo^T + bo   (1 mma: aoh @ Woh)
// ---------------------------------------------------------------------------
__global__ void __launch_bounds__(256, 2) out_mma_kernel(
    const float* __restrict__ x, const float* __restrict__ bo, float* __restrict__ out)
{
    extern __shared__ char dsm[];
    int tid = threadIdx.x;
    int m0 = blockIdx.y * 128;
    int n0 = blockIdx.x * 128;

    float acc[2][8][4] = {};
    gemm_core(g_aoh + (size_t)m0 * DD,
              g_wh + (size_t)3 * DD * DD + (size_t)n0 * DD,
              dsm, acc, tid);

    int lane = tid & 31;
    int w = tid >> 5, wm = w & 3, wn = w >> 2;
    #pragma unroll
    for (int mt = 0; mt < 2; mt++) {
        #pragma unroll
        for (int nt = 0; nt < 8; nt++) {
            int r = m0 + wm * 32 + mt * 16 + (lane >> 2);
            int c = n0 + wn * 64 + nt * 8 + (lane & 3) * 2;
            float b0 = bo[c], b1 = bo[c + 1];
            #pragma unroll
            for (int rr = 0; rr < 2; rr++) {
                int row = r + rr * 8;
                const float* xp = x + (size_t)row * DD + c;
                float* p = out + (size_t)row * DD + c;
                float2 xv = *(const float2*)xp;
                float2 v;
                v.x = acc[mt][nt][rr * 2 + 0] + b0 + xv.x;
                v.y = acc[mt][nt][rr * 2 + 1] + b1 + xv.y;
                *(float2*)p = v;
            }
        }
    }
}

// ---------------------------------------------------------------------------
// Tensor-core flash attention (causal), FIXED-MAX exp2 softmax (M=16).
// q-tile 128 (8 warps x 16 rows), k-tile 64, 4-stage cp.async K/V pipeline,
// TWO k-tiles processed per __syncthreads (cross-tile ILP).
// ---------------------------------------------------------------------------
#define VPITCH 72                    // elements (144 B)
#define KVHALF (64 * VPITCH * 2)     // 9216 B
#define KVSTAGE (2 * KVHALF)         // 18432 B
#define ATTN_DSMEM (4 * KVSTAGE)     // 73728 B
#define SMAX 16.0f

__global__ void __launch_bounds__(256, 2) attn_mma_kernel() {
    extern __shared__ char kvsm[];
    __shared__ __nv_bfloat16 Qs[128 * VPITCH];

    int tid = threadIdx.x;
    int lane = tid & 31;
    int w = tid >> 5;
    int qt = gridDim.x - 1 - blockIdx.x;   // heavy tiles first
    int bh = blockIdx.y;
    int q0 = qt * 128;

    const __nv_bfloat16* Qg = g_qb + (size_t)bh * TT * HD;
    const __nv_bfloat16* Kg = g_kb + (size_t)bh * TT * HD;
    const __nv_bfloat16* Vg = g_vb + (size_t)bh * TT * HD;

    uint32_t kv0 = smem_u32(kvsm);

    auto kv_issue = [&](int kt, int s) {
        uint32_t base = kv0 + s * KVSTAGE;
        #pragma unroll
        for (int u = 0; u < 2; u++) {
            int idx = u * 256 + tid;
            int r = idx >> 3, sg = idx & 7;
            size_t ge = (size_t)(kt * 64 + r) * HD + sg * 8;
            uint32_t so = (uint32_t)(r * 144 + sg * 16);
            cp16(base + so,          Kg + ge);
            cp16(base + KVHALF + so, Vg + ge);
        }
        cp_commit();
    };

    int nkt = 2 * qt + 2;                  // always even
    kv_issue(0, 0);
    kv_issue(1, 1);

    // load Q tile (128 x 64), coalesced
    #pragma unroll
    for (int u = 0; u < 4; u++) {
        int idx = u * 256 + tid;
        int r = idx >> 3, sg = (idx & 7) * 8;
        *(uint4*)(Qs + r * VPITCH + sg) = *(const uint4*)(Qg + (size_t)(q0 + r) * HD + sg);
    }

    int a_row = lane & 15, a_cg = (lane >> 4) * 8;
    uint32_t Qs_u = smem_u32(Qs);
    int quad = lane >> 3;
    int b_row = (lane & 7) + ((quad & 2) ? 8 : 0);   // non-trans (K)
    int b_col = (quad & 1) ? 8 : 0;
    int t_row = (lane & 7) + ((quad & 1) ? 8 : 0);   // trans (V)
    int t_col = (quad & 2) ? 8 : 0;

    float l_[2] = {0.f, 0.f};
    float o[8][4] = {};
    int r0g = q0 + w * 16 + (lane >> 2);
    int warp_max_row = q0 + w * 16 + 15;

    for (int kt = 0; kt < nkt; kt += 2) {
        cp_wait0();          // tiles kt, kt+1 are the only pending groups
        __syncthreads();     // all warps done reading stages (kt+2)&3,(kt+3)&3 (from iter kt-2)
        if (kt + 2 < nkt) {
            kv_issue(kt + 2, (kt + 2) & 3);
            kv_issue(kt + 3, (kt + 3) & 3);
        }

        #pragma unroll
        for (int sub = 0; sub < 2; sub++) {
            int kti = kt + sub;
            if (kti * 64 > warp_max_row) continue;   // fully masked for this warp

            uint32_t Ks_u = kv0 + (kti & 3) * KVSTAGE;
            uint32_t Vs_u = Ks_u + KVHALF;

            // S = Q K^T  (log2 domain)
            float s_[8][4] = {};
            #pragma unroll
            for (int sk = 0; sk < 4; sk++) {
                uint32_t aq[4];
                ldm_x4(aq, Qs_u + (uint32_t)((w * 16 + a_row) * VPITCH + sk * 16 + a_cg) * 2);
                #pragma unroll
                for (int nt2 = 0; nt2 < 4; nt2++) {
                    uint32_t bk[4];
                    ldm_x4(bk, Ks_u + (uint32_t)((nt2 * 16 + b_row) * VPITCH + sk * 16 + b_col) * 2);
                    mma16816(s_[nt2*2],   aq, bk[0], bk[1]);
                    mma16816(s_[nt2*2+1], aq, bk[2], bk[3]);
                }
            }

            // causal mask
            if (kti * 64 + 63 > r0g) {
                #pragma unroll
                for (int nt = 0; nt < 8; nt++) {
                    int c = kti * 64 + nt * 8 + (lane & 3) * 2;
                    if (c     > r0g)     s_[nt][0] = -1e30f;
                    if (c + 1 > r0g)     s_[nt][1] = -1e30f;
                    if (c     > r0g + 8) s_[nt][2] = -1e30f;
                    if (c + 1 > r0g + 8) s_[nt][3] = -1e30f;
                }
            }

            // fixed-max exponentiation: p = 2^(s - 16)
            #pragma unroll
            for (int ri = 0; ri < 2; ri++) {
                float rs = 0.f;
                #pragma unroll
                for (int nt = 0; nt < 8; nt++) {
                    float p0 = exp2f(s_[nt][ri*2]   - SMAX);
                    float p1 = exp2f(s_[nt][ri*2+1] - SMAX);
                    s_[nt][ri*2] = p0; s_[nt][ri*2+1] = p1;
                    rs += p0 + p1;
                }
                l_[ri] += rs;
            }

            // pack P into A-fragments
            uint32_t ap[4][4];
            #pragma unroll
            for (int j = 0; j < 4; j++) {
                ap[j][0] = packbf(s_[2*j][0],   s_[2*j][1]);
                ap[j][1] = packbf(s_[2*j][2],   s_[2*j][3]);
                ap[j][2] = packbf(s_[2*j+1][0], s_[2*j+1][1]);
                ap[j][3] = packbf(s_[2*j+1][2], s_[2*j+1][3]);
            }

            // O += P V
            #pragma unroll
            for (int j = 0; j < 4; j++) {
                #pragma unroll
                for (int dt2 = 0; dt2 < 4; dt2++) {
                    uint32_t bv[4];
                    ldm_x4_t(bv, Vs_u + (uint32_t)((j * 16 + t_row) * VPITCH + dt2 * 16 + t_col) * 2);
                    mma16816(o[dt2*2],   ap[j], bv[0], bv[1]);
                    mma16816(o[dt2*2+1], ap[j], bv[2], bv[3]);
                }
            }
        }
    }

    // epilogue: cross-quad l reduction, normalize, write bf16 [B*T, D]
    int b = bh / HH, h = bh % HH;
    #pragma unroll
    for (int ri = 0; ri < 2; ri++) {
        float lt = l_[ri];
        lt += __shfl_xor_sync(0xffffffffu, lt, 1);
        lt += __shfl_xor_sync(0xffffffffu, lt, 2);
        float inv = 1.0f / lt;
        int qg = q0 + w * 16 + (lane >> 2) + ri * 8;
        size_t base = ((size_t)(b * TT + qg)) * DD + h * HD;
        #pragma unroll
        for (int nt = 0; nt < 8; nt++) {
            int c = nt * 8 + (lane & 3) * 2;
            float v0 = o[nt][ri*2] * inv, v1 = o[nt][ri*2+1] * inv;
            *(__nv_bfloat162*)(g_aoh + base + c) = __floats2bfloat162_rn(v0, v1);
        }
    }
}

// ---------------------------------------------------------------------------
extern "C" void kernel_launch(void* const* d_in, const int* in_sizes, int n_in,
                              void* d_out, int out_size) {
    const float* x     = (const float*)d_in[0];
    const float* bq    = (const float*)d_in[2];
    const float* bk    = (const float*)d_in[4];
    const float* bv    = (const float*)d_in[6];
    const float* bo    = (const float*)d_in[8];
    const float* gamma = (const float*)d_in[9];
    const float* beta  = (const float*)d_in[10];
    float* out = (float*)d_out;

    cudaFuncSetAttribute(qkv_mma_kernel, cudaFuncAttributeMaxDynamicSharedMemorySize, GEMM_DSMEM);
    cudaFuncSetAttribute(out_mma_kernel, cudaFuncAttributeMaxDynamicSharedMemorySize, GEMM_DSMEM);
    cudaFuncSetAttribute(attn_mma_kernel, cudaFuncAttributeMaxDynamicSharedMemorySize, ATTN_DSMEM);

    ln_kernel<<<NR, 256>>>(x, gamma, beta);

    dim3 wgrid(1024, 4);
    wconv_kernel<<<wgrid, 256>>>((const float*)d_in[1], (const float*)d_in[3],
                                 (const float*)d_in[5], (const float*)d_in[7]);

    dim3 grid_qkv(DD / 128, NR / 128, 3);
    qkv_mma_kernel<<<grid_qkv, 256, GEMM_DSMEM>>>(bq, bk, bv);

    dim3 grid_attn(TT / 128, BB * HH);
    attn_mma_kernel<<<grid_attn, 256, ATTN_DSMEM>>>();

    dim3 grid_out(DD / 128, NR / 128);
    out_mma_kernel<<<grid_out, 256, GEMM_DSMEM>>>(x, bo, out);
}

// round 14
// speedup vs baseline: 1.0106x; 1.0106x over previous
#include <cuda_runtime.h>
#include <cuda_bf16.h>
#include <cstdint>

#define BB 4
#define TT 2048
#define DD 1024
#define HH 16
#define HD 64
#define NR (BB*TT)   // 8192

// ---------------- device scratch (allocation-free rule) ----------------
__device__ __nv_bfloat16 g_qb[NR*DD];        // [B,H,T,HD] bf16 (q pre-scaled by 0.125*log2e)
__device__ __nv_bfloat16 g_kb[NR*DD];
__device__ __nv_bfloat16 g_vb[NR*DD];
__device__ __nv_bfloat16 g_xnh[NR*DD];       // layernormed x, bf16
__device__ __nv_bfloat16 g_aoh[NR*DD];       // attention out bf16 [B*T, D]
__device__ __nv_bfloat16 g_wh[4u*DD*DD];     // Wq,Wk,Wv,Wo bf16

__device__ __forceinline__ uint32_t smem_u32(const void* p) {
    uint32_t a;
    asm("{ .reg .u64 t; cvta.to.shared.u64 t, %1; cvt.u32.u64 %0, t; }" : "=r"(a) : "l"(p));
    return a;
}
__device__ __forceinline__ uint32_t packbf(float a, float b) {
    __nv_bfloat162 t = __floats2bfloat162_rn(a, b);
    return *(uint32_t*)&t;
}

// mma / ldmatrix / cp.async helpers
__device__ __forceinline__ void mma16816(float (&c)[4], const uint32_t (&a)[4],
                                         uint32_t b0, uint32_t b1) {
    asm volatile(
        "mma.sync.aligned.m16n8k16.row.col.f32.bf16.bf16.f32 "
        "{%0,%1,%2,%3},{%4,%5,%6,%7},{%8,%9},{%0,%1,%2,%3};"
        : "+f"(c[0]), "+f"(c[1]), "+f"(c[2]), "+f"(c[3])
        : "r"(a[0]), "r"(a[1]), "r"(a[2]), "r"(a[3]), "r"(b0), "r"(b1));
}
__device__ __forceinline__ void ldm_x4(uint32_t (&r)[4], uint32_t addr) {
    asm volatile("ldmatrix.sync.aligned.m8n8.x4.shared.b16 {%0,%1,%2,%3}, [%4];"
                 : "=r"(r[0]), "=r"(r[1]), "=r"(r[2]), "=r"(r[3]) : "r"(addr));
}
__device__ __forceinline__ void ldm_x4_t(uint32_t (&r)[4], uint32_t addr) {
    asm volatile("ldmatrix.sync.aligned.m8n8.x4.trans.shared.b16 {%0,%1,%2,%3}, [%4];"
                 : "=r"(r[0]), "=r"(r[1]), "=r"(r[2]), "=r"(r[3]) : "r"(addr));
}
__device__ __forceinline__ void cp16(uint32_t s, const void* g) {
    asm volatile("cp.async.cg.shared.global [%0], [%1], 16;" :: "r"(s), "l"(g));
}
__device__ __forceinline__ void cp_commit() { asm volatile("cp.async.commit_group;"); }
__device__ __forceinline__ void cp_wait1()  { asm volatile("cp.async.wait_group 1;"); }
__device__ __forceinline__ void cp_wait0()  { asm volatile("cp.async.wait_group 0;"); }

// ---------------------------------------------------------------------------
// Fused prep: blocks [0, NR) do LayerNorm rows; blocks [NR, NR+4096) convert
// the four weight matrices to bf16. Independent work, packed into one launch.
// ---------------------------------------------------------------------------
__global__ void prep_kernel(const float* __restrict__ x,
                            const float* __restrict__ gamma,
                            const float* __restrict__ beta,
                            const float* __restrict__ Wq, const float* __restrict__ Wk,
                            const float* __restrict__ Wv, const float* __restrict__ Wo) {
    int bid = blockIdx.x;
    int t = threadIdx.x;

    if (bid >= NR) {
        // ---- weight convert ----
        int wbid = bid - NR;                 // 0..4095
        int m = wbid >> 10;                  // matrix id
        const float* W = (m == 0) ? Wq : (m == 1) ? Wk : (m == 2) ? Wv : Wo;
        size_t base = (size_t)m * DD * DD;
        int idx = (wbid & 1023) * 256 + t;   // float4 index
        float4 v = ((const float4*)W)[idx];
        __nv_bfloat162* dh = (__nv_bfloat162*)(g_wh + base + (size_t)idx * 4);
        dh[0] = __floats2bfloat162_rn(v.x, v.y);
        dh[1] = __floats2bfloat162_rn(v.z, v.w);
        return;
    }

    // ---- layernorm ----
    int row = bid;
    const float4* xr = (const float4*)(x + (size_t)row * DD);
    float4 v = xr[t];
    float s  = v.x + v.y + v.z + v.w;
    float sq = v.x*v.x + v.y*v.y + v.z*v.z + v.w*v.w;

    __shared__ float red0[8], red1[8];
    #pragma unroll
    for (int o = 16; o > 0; o >>= 1) {
        s  += __shfl_xor_sync(0xffffffffu, s,  o);
        sq += __shfl_xor_sync(0xffffffffu, sq, o);
    }
    int w = t >> 5, l = t & 31;
    if (l == 0) { red0[w] = s; red1[w] = sq; }
    __syncthreads();
    __shared__ float smu, srs;
    if (t < 32) {
        float a  = (t < 8) ? red0[t] : 0.f;
        float b2 = (t < 8) ? red1[t] : 0.f;
        #pragma unroll
        for (int o = 4; o > 0; o >>= 1) {
            a  += __shfl_xor_sync(0xffffffffu, a,  o);
            b2 += __shfl_xor_sync(0xffffffffu, b2, o);
        }
        if (t == 0) {
            float mu = a * (1.0f / DD);
            float var = b2 * (1.0f / DD) - mu * mu;
            smu = mu; srs = rsqrtf(var + 1e-5f);
        }
    }
    __syncthreads();
    float mu = smu, rs = srs;
    float4 gv = ((const float4*)gamma)[t];
    float4 bv = ((const float4*)beta)[t];
    float o0 = (v.x - mu) * rs * gv.x + bv.x;
    float o1 = (v.y - mu) * rs * gv.y + bv.y;
    float o2 = (v.z - mu) * rs * gv.z + bv.z;
    float o3 = (v.w - mu) * rs * gv.w + bv.w;
    size_t off = (size_t)row * DD + t * 4;
    ((__nv_bfloat162*)(g_xnh + off))[0] = __floats2bfloat162_rn(o0, o1);
    ((__nv_bfloat162*)(g_xnh + off))[1] = __floats2bfloat162_rn(o2, o3);
}

// ---------------------------------------------------------------------------
// Tensor-core GEMM core (R12 measured-best). 128x128 tile, k-chunk 32,
// 8 warps 4(m)x2(n). 3-stage cp.async pipeline, ONE __syncthreads per chunk.
// acc = Ah @ Bh^T (1 mma). Stage: Ah, Bh (20480 B), row pitch 80 B.
// ---------------------------------------------------------------------------
#define SPITCH 40            // elements per row (80 bytes)
#define GMATB  10240
#define GSTAGEB (2 * GMATB)          // 20480
#define GEMM_DSMEM (3 * GSTAGEB)     // 61440
#define NKC (DD / 32)                // 32

__device__ __forceinline__ void gemm_issue(
    const __nv_bfloat16* Ahg, const __nv_bfloat16* Bhg,
    uint32_t base, int kc, int tid)
{
    #pragma unroll
    for (int u = 0; u < 2; u++) {
        int idx = tid * 2 + u;                 // 0..511
        int row = idx >> 2;
        int sg  = idx & 3;                     // 16B segment
        uint32_t so = (uint32_t)(row * 80 + sg * 16);
        size_t ge = (size_t)row * DD + kc * 32 + sg * 8;
        cp16(base + so,         Ahg + ge);
        cp16(base + GMATB + so, Bhg + ge);
    }
    cp_commit();
}

__device__ __forceinline__ void gemm_core(
    const __nv_bfloat16* __restrict__ Ahg, const __nv_bfloat16* __restrict__ Bhg,
    char* dsm, float (&acc)[2][8][4], int tid)
{
    int lane = tid & 31;
    int w = tid >> 5;
    int wm = w & 3;
    int wn = w >> 2;

    uint32_t sb0 = smem_u32(dsm);
    int a_row = (lane & 15), a_cg = (lane >> 4) * 8;
    int quad = lane >> 3;
    int b_row = (lane & 7) + ((quad & 2) ? 8 : 0);
    int b_col = (quad & 1) ? 8 : 0;

    gemm_issue(Ahg, Bhg, sb0,           0, tid);
    gemm_issue(Ahg, Bhg, sb0 + GSTAGEB, 1, tid);

    for (int kc = 0; kc < NKC; kc++) {
        if (kc < NKC - 1) cp_wait1(); else cp_wait0();
        __syncthreads();
        if (kc + 2 < NKC)
            gemm_issue(Ahg, Bhg, sb0 + ((kc + 2) % 3) * GSTAGEB, kc + 2, tid);

        uint32_t Ah_u = sb0 + (kc % 3) * GSTAGEB;
        uint32_t Bh_u = Ah_u + GMATB;

        #pragma unroll
        for (int ks = 0; ks < 2; ks++) {
            uint32_t ah[2][4];
            #pragma unroll
            for (int mt = 0; mt < 2; mt++) {
                uint32_t off = (uint32_t)((wm * 32 + mt * 16 + a_row) * SPITCH + ks * 16 + a_cg) * 2;
                ldm_x4(ah[mt], Ah_u + off);
            }
            #pragma unroll
            for (int nt2 = 0; nt2 < 4; nt2++) {
                uint32_t boff = (uint32_t)((wn * 64 + nt2 * 16 + b_row) * SPITCH + ks * 16 + b_col) * 2;
                uint32_t bh[4];
                ldm_x4(bh, Bh_u + boff);
                int n0t = nt2 * 2, n1t = nt2 * 2 + 1;
                mma16816(acc[0][n0t], ah[0], bh[0], bh[1]);
                mma16816(acc[1][n0t], ah[1], bh[0], bh[1]);
                mma16816(acc[0][n1t], ah[0], bh[2], bh[3]);
                mma16816(acc[1][n1t], ah[1], bh[2], bh[3]);
            }
        }
    }
    __syncthreads();
}

// ---------------------------------------------------------------------------
// QKV projection -> bf16 [B,H,T,HD]; q pre-scaled by 0.125*log2e
// ---------------------------------------------------------------------------
__global__ void __launch_bounds__(256, 2) qkv_mma_kernel(
    const float* __restrict__ bq, const float* __restrict__ bk, const float* __restrict__ bv)
{
    extern __shared__ char dsm[];
    int tid = threadIdx.x;
    int z = blockIdx.z;
    int m0 = blockIdx.y * 128;
    int n0 = blockIdx.x * 128;

    const float* bias; __nv_bfloat16* dst; float sc;
    if (z == 0)      { bias = bq; dst = g_qb; sc = 0.125f * 1.44269504089f; }
    else if (z == 1) { bias = bk; dst = g_kb; sc = 1.0f; }
    else             { bias = bv; dst = g_vb; sc = 1.0f; }

    float acc[2][8][4] = {};
    gemm_core(g_xnh + (size_t)m0 * DD,
              g_wh + (size_t)z * DD * DD + (size_t)n0 * DD,
              dsm, acc, tid);

    int lane = tid & 31;
    int w = tid >> 5, wm = w & 3, wn = w >> 2;
    #pragma unroll
    for (int mt = 0; mt < 2; mt++) {
        #pragma unroll
        for (int nt = 0; nt < 8; nt++) {
            int r = m0 + wm * 32 + mt * 16 + (lane >> 2);
            int c = n0 + wn * 64 + nt * 8 + (lane & 3) * 2;
            float b0 = bias[c], b1 = bias[c + 1];
            #pragma unroll
            for (int rr = 0; rr < 2; rr++) {
                int row = r + rr * 8;
                int b = row >> 11, t = row & (TT - 1);
                int h = c >> 6, hd = c & 63;
                __nv_bfloat16* p = dst + (((size_t)(b * HH + h)) * TT + t) * HD + hd;
                float vx = (acc[mt][nt][rr * 2 + 0] + b0) * sc;
                float vy = (acc[mt][nt][rr * 2 + 1] + b1) * sc;
                *(__nv_bfloat162*)p = __floats2bfloat162_rn(vx, vy);
            }
        }
    }
}

// ---------------------------------------------------------------------------
// Output projection: out = x + ao @ Wo^T + bo   (1 mma: aoh @ Woh)
// ---------------------------------------------------------------------------
__global__ void __launch_bounds__(256, 2) out_mma_kernel(
    const float* __restrict__ x, const float* __restrict__ bo, float* __restrict__ out)
{
    extern __shared__ char dsm[];
    int tid = threadIdx.x;
    int m0 = blockIdx.y * 128;
    int n0 = blockIdx.x * 128;

    float acc[2][8][4] = {};
    gemm_core(g_aoh + (size_t)m0 * DD,
              g_wh + (size_t)3 * DD * DD + (size_t)n0 * DD,
              dsm, acc, tid);

    int lane = tid & 31;
    int w = tid >> 5, wm = w & 3, wn = w >> 2;
    #pragma unroll
    for (int mt = 0; mt < 2; mt++) {
        #pragma unroll
        for (int nt = 0; nt < 8; nt++) {
            int r = m0 + wm * 32 + mt * 16 + (lane >> 2);
            int c = n0 + wn * 64 + nt * 8 + (lane & 3) * 2;
            float b0 = bo[c], b1 = bo[c + 1];
            #pragma unroll
            for (int rr = 0; rr < 2; rr++) {
                int row = r + rr * 8;
                const float* xp = x + (size_t)row * DD + c;
                float* p = out + (size_t)row * DD + c;
                float2 xv = *(const float2*)xp;
                float2 v;
                v.x = acc[mt][nt][rr * 2 + 0] + b0 + xv.x;
                v.y = acc[mt][nt][rr * 2 + 1] + b1 + xv.y;
                *(float2*)p = v;
            }
        }
    }
}

// ---------------------------------------------------------------------------
// Tensor-core flash attention (causal), FIXED-MAX exp2 softmax (M=16).
// R12 measured-best loop: 3-stage cp.async, one k-tile per __syncthreads.
// ---------------------------------------------------------------------------
#define VPITCH 72                    // elements (144 B)
#define KVHALF (64 * VPITCH * 2)     // 9216 B
#define KVSTAGE (2 * KVHALF)         // 18432 B
#define ATTN_DSMEM (3 * KVSTAGE)     // 55296 B
#define SMAX 16.0f

__global__ void __launch_bounds__(256, 2) attn_mma_kernel() {
    extern __shared__ char kvsm[];
    __shared__ __nv_bfloat16 Qs[128 * VPITCH];

    int tid = threadIdx.x;
    int lane = tid & 31;
    int w = tid >> 5;
    int qt = gridDim.x - 1 - blockIdx.x;   // heavy tiles first
    int bh = blockIdx.y;
    int q0 = qt * 128;

    const __nv_bfloat16* Qg = g_qb + (size_t)bh * TT * HD;
    const __nv_bfloat16* Kg = g_kb + (size_t)bh * TT * HD;
    const __nv_bfloat16* Vg = g_vb + (size_t)bh * TT * HD;

    uint32_t kv0 = smem_u32(kvsm);

    auto kv_issue = [&](int kt, int s) {
        uint32_t base = kv0 + s * KVSTAGE;
        #pragma unroll
        for (int u = 0; u < 2; u++) {
            int idx = u * 256 + tid;
            int r = idx >> 3, sg = idx & 7;
            size_t ge = (size_t)(kt * 64 + r) * HD + sg * 8;
            uint32_t so = (uint32_t)(r * 144 + sg * 16);
            cp16(base + so,          Kg + ge);
            cp16(base + KVHALF + so, Vg + ge);
        }
        cp_commit();
    };

    int nkt = 2 * qt + 2;
    kv_issue(0, 0);
    kv_issue(1, 1);

    // load Q tile (128 x 64), coalesced
    #pragma unroll
    for (int u = 0; u < 4; u++) {
        int idx = u * 256 + tid;
        int r = idx >> 3, sg = (idx & 7) * 8;
        *(uint4*)(Qs + r * VPITCH + sg) = *(const uint4*)(Qg + (size_t)(q0 + r) * HD + sg);
    }

    int a_row = lane & 15, a_cg = (lane >> 4) * 8;
    uint32_t Qs_u = smem_u32(Qs);
    int quad = lane >> 3;
    int b_row = (lane & 7) + ((quad & 2) ? 8 : 0);   // non-trans (K)
    int b_col = (quad & 1) ? 8 : 0;
    int t_row = (lane & 7) + ((quad & 1) ? 8 : 0);   // trans (V)
    int t_col = (quad & 2) ? 8 : 0;

    float l_[2] = {0.f, 0.f};
    float o[8][4] = {};
    int r0g = q0 + w * 16 + (lane >> 2);
    int warp_max_row = q0 + w * 16 + 15;

    for (int kt = 0; kt < nkt; kt++) {
        if (kt < nkt - 1) cp_wait1(); else cp_wait0();
        __syncthreads();
        if (kt + 2 < nkt) kv_issue(kt + 2, (kt + 2) % 3);

        if (kt * 64 > warp_max_row) continue;   // fully masked for this warp

        uint32_t Ks_u = kv0 + (kt % 3) * KVSTAGE;
        uint32_t Vs_u = Ks_u + KVHALF;

        // S = Q K^T  (log2 domain)
        float s_[8][4] = {};
        #pragma unroll
        for (int sk = 0; sk < 4; sk++) {
            uint32_t aq[4];
            ldm_x4(aq, Qs_u + (uint32_t)((w * 16 + a_row) * VPITCH + sk * 16 + a_cg) * 2);
            #pragma unroll
            for (int nt2 = 0; nt2 < 4; nt2++) {
                uint32_t bk[4];
                ldm_x4(bk, Ks_u + (uint32_t)((nt2 * 16 + b_row) * VPITCH + sk * 16 + b_col) * 2);
                mma16816(s_[nt2*2],   aq, bk[0], bk[1]);
                mma16816(s_[nt2*2+1], aq, bk[2], bk[3]);
            }
        }

        // causal mask
        if (kt * 64 + 63 > r0g) {
            #pragma unroll
            for (int nt = 0; nt < 8; nt++) {
                int c = kt * 64 + nt * 8 + (lane & 3) * 2;
                if (c     > r0g)     s_[nt][0] = -1e30f;
                if (c + 1 > r0g)     s_[nt][1] = -1e30f;
                if (c     > r0g + 8) s_[nt][2] = -1e30f;
                if (c + 1 > r0g + 8) s_[nt][3] = -1e30f;
            }
        }

        // fixed-max exponentiation: p = 2^(s - 16)
        #pragma unroll
        for (int ri = 0; ri < 2; ri++) {
            float rs = 0.f;
            #pragma unroll
            for (int nt = 0; nt < 8; nt++) {
                float p0 = exp2f(s_[nt][ri*2]   - SMAX);
                float p1 = exp2f(s_[nt][ri*2+1] - SMAX);
                s_[nt][ri*2] = p0; s_[nt][ri*2+1] = p1;
                rs += p0 + p1;
            }
            l_[ri] += rs;
        }

        // pack P into A-fragments
        uint32_t ap[4][4];
        #pragma unroll
        for (int j = 0; j < 4; j++) {
            ap[j][0] = packbf(s_[2*j][0],   s_[2*j][1]);
            ap[j][1] = packbf(s_[2*j][2],   s_[2*j][3]);
            ap[j][2] = packbf(s_[2*j+1][0], s_[2*j+1][1]);
            ap[j][3] = packbf(s_[2*j+1][2], s_[2*j+1][3]);
        }

        // O += P V
        #pragma unroll
        for (int j = 0; j < 4; j++) {
            #pragma unroll
            for (int dt2 = 0; dt2 < 4; dt2++) {
                uint32_t bv[4];
                ldm_x4_t(bv, Vs_u + (uint32_t)((j * 16 + t_row) * VPITCH + dt2 * 16 + t_col) * 2);
                mma16816(o[dt2*2],   ap[j], bv[0], bv[1]);
                mma16816(o[dt2*2+1], ap[j], bv[2], bv[3]);
            }
        }
    }

    // epilogue: cross-quad l reduction, normalize, write bf16 [B*T, D]
    int b = bh / HH, h = bh % HH;
    #pragma unroll
    for (int ri = 0; ri < 2; ri++) {
        float lt = l_[ri];
        lt += __shfl_xor_sync(0xffffffffu, lt, 1);
        lt += __shfl_xor_sync(0xffffffffu, lt, 2);
        float inv = 1.0f / lt;
        int qg = q0 + w * 16 + (lane >> 2) + ri * 8;
        size_t base = ((size_t)(b * TT + qg)) * DD + h * HD;
        #pragma unroll
        for (int nt = 0; nt < 8; nt++) {
            int c = nt * 8 + (lane & 3) * 2;
            float v0 = o[nt][ri*2] * inv, v1 = o[nt][ri*2+1] * inv;
            *(__nv_bfloat162*)(g_aoh + base + c) = __floats2bfloat162_rn(v0, v1);
        }
    }
}

// ---------------------------------------------------------------------------
extern "C" void kernel_launch(void* const* d_in, const int* in_sizes, int n_in,
                              void* d_out, int out_size) {
    const float* x     = (const float*)d_in[0];
    const float* bq    = (const float*)d_in[2];
    const float* bk    = (const float*)d_in[4];
    const float* bv    = (const float*)d_in[6];
    const float* bo    = (const float*)d_in[8];
    const float* gamma = (const float*)d_in[9];
    const float* beta  = (const float*)d_in[10];
    float* out = (float*)d_out;

    cudaFuncSetAttribute(qkv_mma_kernel, cudaFuncAttributeMaxDynamicSharedMemorySize, GEMM_DSMEM);
    cudaFuncSetAttribute(out_mma_kernel, cudaFuncAttributeMaxDynamicSharedMemorySize, GEMM_DSMEM);
    cudaFuncSetAttribute(attn_mma_kernel, cudaFuncAttributeMaxDynamicSharedMemorySize, ATTN_DSMEM);

    // fused LN + weight-convert (independent work, one wave-packed launch)
    prep_kernel<<<NR + 4096, 256>>>(x, gamma, beta,
                                    (const float*)d_in[1], (const float*)d_in[3],
                                    (const float*)d_in[5], (const float*)d_in[7]);

    dim3 grid_qkv(DD / 128, NR / 128, 3);
    qkv_mma_kernel<<<grid_qkv, 256, GEMM_DSMEM>>>(bq, bk, bv);

    dim3 grid_attn(TT / 128, BB * HH);
    attn_mma_kernel<<<grid_attn, 256, ATTN_DSMEM>>>();

    dim3 grid_out(DD / 128, NR / 128);
    out_mma_kernel<<<grid_out, 256, GEMM_DSMEM>>>(x, bo, out);
}